// round 11
// baseline (speedup 1.0000x reference)
#include <cuda_runtime.h>
#include <cuda_bf16.h>
#include <cstdint>

#define Bsz 4
#define Cc  128
#define Hh  64
#define Ww  64
#define Kk  7
#define NHh 8
#define DHh 16
#define PADk 3
#define HW  (Hh*Ww)        // 4096
#define CHW (Cc*HW)        // 524288

typedef unsigned long long ull;

// scratch for projections, CHANNEL-LAST layout [b][hw][c]
__device__ float g_q[Bsz*CHW];
__device__ float g_k[Bsz*CHW];
__device__ float g_v[Bsz*CHW];

#define LDK 136                          // padded bf16 row length (272 B)
#define WIMG (128 * LDK)                 // ushorts per image (17408)
// pre-packed W: [proj][hi|lo] images in the exact smem layout
__device__ unsigned short g_wpack[3 * 2 * WIMG];

// ---------------- packed f32x2 helpers ----------------
__device__ __forceinline__ ull fma2(ull a, ull b, ull c) {
    ull d; asm("fma.rn.f32x2 %0, %1, %2, %3;" : "=l"(d) : "l"(a), "l"(b), "l"(c)); return d;
}
__device__ __forceinline__ ull add2(ull a, ull b) {
    ull d; asm("add.rn.f32x2 %0, %1, %2;" : "=l"(d) : "l"(a), "l"(b)); return d;
}
__device__ __forceinline__ ull pack2(float lo, float hi) {
    ull d; asm("mov.b64 %0, {%1, %2};" : "=l"(d) : "f"(lo), "f"(hi)); return d;
}
__device__ __forceinline__ float2 unpack2(ull v) {
    float2 r; asm("mov.b64 {%0, %1}, %2;" : "=f"(r.x), "=f"(r.y) : "l"(v)); return r;
}

// ---------------- HMMA helpers (sm_80+) ----------------
__device__ __forceinline__ uint32_t smem_u32(const void* p) {
    uint32_t a;
    asm("{ .reg .u64 t; cvta.to.shared.u64 t, %1; cvt.u32.u64 %0, t; }" : "=r"(a) : "l"(p));
    return a;
}
__device__ __forceinline__ void ldsm_x4(uint32_t& r0, uint32_t& r1, uint32_t& r2,
                                        uint32_t& r3, uint32_t addr) {
    asm volatile("ldmatrix.sync.aligned.m8n8.x4.shared.b16 {%0,%1,%2,%3}, [%4];"
                 : "=r"(r0), "=r"(r1), "=r"(r2), "=r"(r3) : "r"(addr));
}
__device__ __forceinline__ void mma_bf16(float* c, const uint32_t* a, const uint32_t* b) {
    asm volatile(
        "mma.sync.aligned.m16n8k16.row.col.f32.bf16.bf16.f32 "
        "{%0,%1,%2,%3}, {%4,%5,%6,%7}, {%8,%9}, {%0,%1,%2,%3};"
        : "+f"(c[0]), "+f"(c[1]), "+f"(c[2]), "+f"(c[3])
        : "r"(a[0]), "r"(a[1]), "r"(a[2]), "r"(a[3]), "r"(b[0]), "r"(b[1]));
}

// ---------------------------------------------------------------------------
// Kernel 0: pack W fp32 -> bf16 hi/lo images.  Grid = 48.
// ---------------------------------------------------------------------------
__global__ void wpack_kernel(const float* __restrict__ wq,
                             const float* __restrict__ wk,
                             const float* __restrict__ wv) {
    const int proj  = blockIdx.x >> 4;
    const int chunk = blockIdx.x & 15;
    const float* W = (proj == 0) ? wq : (proj == 1) ? wk : wv;
    unsigned short* hi = g_wpack + proj * 2 * WIMG;
    unsigned short* lo = hi + WIMG;
    int e = chunk * 1024 + threadIdx.x * 4;
    int m = e >> 7, c = e & 127;
    float4 v4 = *(const float4*)&W[e];
    ushort4 h4, l4;
    __nv_bfloat16 h;
    h = __float2bfloat16(v4.x); h4.x = __bfloat16_as_ushort(h);
    l4.x = __bfloat16_as_ushort(__float2bfloat16(v4.x - __bfloat162float(h)));
    h = __float2bfloat16(v4.y); h4.y = __bfloat16_as_ushort(h);
    l4.y = __bfloat16_as_ushort(__float2bfloat16(v4.y - __bfloat162float(h)));
    h = __float2bfloat16(v4.z); h4.z = __bfloat16_as_ushort(h);
    l4.z = __bfloat16_as_ushort(__float2bfloat16(v4.z - __bfloat162float(h)));
    h = __float2bfloat16(v4.w); h4.w = __bfloat16_as_ushort(h);
    l4.w = __bfloat16_as_ushort(__float2bfloat16(v4.w - __bfloat162float(h)));
    *(ushort4*)&hi[m * LDK + c] = h4;
    *(ushort4*)&lo[m * LDK + c] = l4;
}

// ---------------------------------------------------------------------------
// Kernel 1 (R9, proven ~10.4us): fused QKV GEMM via HMMA (bf16 hi/lo).
// Grid = 256 (64 px each, 2 blocks/SM). 8 warps (4m x 2n), warp tile 32x32.
// ---------------------------------------------------------------------------
#define XHI_OFF 0
#define XLO_OFF (64 * LDK * 2)          // 17408
#define WHI_OFF (2 * 64 * LDK * 2)      // 34816
#define WLO_OFF (WHI_OFF + 128 * LDK * 2)
#define GEMM_SMEM (WHI_OFF + 2 * 128 * LDK * 2)   // 104448 B

__global__ __launch_bounds__(256, 2) void qkv_hmma(
    const float* __restrict__ x,
    const float* __restrict__ bq, const float* __restrict__ bk,
    const float* __restrict__ bv)
{
    extern __shared__ char smc[];
    unsigned short* Xhi = (unsigned short*)(smc + XHI_OFF);
    unsigned short* Xlo = (unsigned short*)(smc + XLO_OFF);
    const uint32_t sb = smem_u32(smc);

    const int tid = threadIdx.x;
    const int warp = tid >> 5, lane = tid & 31;
    const int wy = warp >> 1, wx = warp & 1;   // m = wy*32, n = wx*32
    const int n0 = blockIdx.x * 64;
    const int b = n0 >> 12, hw0 = n0 & 4095;
    const float* xb = x + (size_t)b * CHW + hw0;

    // ---- X tile (64 px): fp32 -> bf16 hi/lo, [n][k] ----
    for (int e = tid; e < 8192; e += 256) {
        int c = e >> 6, n = e & 63;
        float v = xb[c * HW + n];
        __nv_bfloat16 h = __float2bfloat16(v);
        __nv_bfloat16 l = __float2bfloat16(v - __bfloat162float(h));
        Xhi[n * LDK + c] = __bfloat16_as_ushort(h);
        Xlo[n * LDK + c] = __bfloat16_as_ushort(l);
    }

#pragma unroll 1
    for (int p = 0; p < 3; p++) {
        const float* bp = (p == 0) ? bq : (p == 1) ? bk : bv;
        float* og = ((p == 0) ? g_q : (p == 1) ? g_k : g_v) + (size_t)n0 * 128;

        __syncthreads();   // X ready (p=0); prior mma reads of W done (p>0)
        // ---- copy W(p) hi+lo images (69632 B, pure float4 copy) ----
        {
            const float4* src = (const float4*)(g_wpack + p * 2 * WIMG);
            float4* dst = (float4*)(smc + WHI_OFF);
#pragma unroll
            for (int i = 0; i < 17; i++) dst[tid + i * 256] = src[tid + i * 256];
        }
        __syncthreads();

        float acc[2][4][4];
#pragma unroll
        for (int i = 0; i < 2; i++)
#pragma unroll
            for (int j = 0; j < 4; j++)
#pragma unroll
                for (int t = 0; t < 4; t++) acc[i][j][t] = 0.f;

#pragma unroll
        for (int k = 0; k < 8; k++) {
            const int kb = k * 16;
            uint32_t ahi[2][4], alo[2][4];
#pragma unroll
            for (int mf = 0; mf < 2; mf++) {
                int row = wy * 32 + mf * 16 + (lane & 15);
                int col = kb + ((lane >> 4) << 3);
                uint32_t off = (uint32_t)(row * LDK + col) * 2;
                ldsm_x4(ahi[mf][0], ahi[mf][1], ahi[mf][2], ahi[mf][3],
                        sb + WHI_OFF + off);
                ldsm_x4(alo[mf][0], alo[mf][1], alo[mf][2], alo[mf][3],
                        sb + WLO_OFF + off);
            }
            uint32_t bhi[4][2], blo[4][2];
#pragma unroll
            for (int nf4 = 0; nf4 < 2; nf4++) {
                int g = lane >> 3;
                int row = wx * 32 + nf4 * 16 + (lane & 7) + ((g & 2) << 2);
                int col = kb + ((g & 1) << 3);
                uint32_t off = (uint32_t)(row * LDK + col) * 2;
                uint32_t r0, r1, r2, r3;
                ldsm_x4(r0, r1, r2, r3, sb + XHI_OFF + off);
                bhi[nf4 * 2][0] = r0; bhi[nf4 * 2][1] = r1;
                bhi[nf4 * 2 + 1][0] = r2; bhi[nf4 * 2 + 1][1] = r3;
                ldsm_x4(r0, r1, r2, r3, sb + XLO_OFF + off);
                blo[nf4 * 2][0] = r0; blo[nf4 * 2][1] = r1;
                blo[nf4 * 2 + 1][0] = r2; blo[nf4 * 2 + 1][1] = r3;
            }
#pragma unroll
            for (int mf = 0; mf < 2; mf++)
#pragma unroll
                for (int nf = 0; nf < 4; nf++) {
                    mma_bf16(acc[mf][nf], ahi[mf], bhi[nf]);
                    mma_bf16(acc[mf][nf], ahi[mf], blo[nf]);
                    mma_bf16(acc[mf][nf], alo[mf], bhi[nf]);
                }
        }

        // ---- epilogue: channel-last store ----
#pragma unroll
        for (int mf = 0; mf < 2; mf++) {
            int r0 = wy * 32 + mf * 16 + (lane >> 2);
            int r1 = r0 + 8;
            float bi0 = bp[r0], bi1 = bp[r1];
#pragma unroll
            for (int nf = 0; nf < 4; nf++) {
                int c0 = wx * 32 + nf * 8 + (lane & 3) * 2;
                float* o0 = og + (size_t)c0 * 128;
                float* o1 = o0 + 128;
                o0[r0] = acc[mf][nf][0] + bi0;
                o1[r0] = acc[mf][nf][1] + bi0;
                o0[r1] = acc[mf][nf][2] + bi1;
                o1[r1] = acc[mf][nf][3] + bi1;
            }
        }
    }
}

// ---------------------------------------------------------------------------
// Kernel 2: local attention — R6 body, retiled 8x32 at 128 threads for
// 3 blocks/SM (24 warps). Thread (tx,ty) owns pixels (h0+ty, w0+2tx) and
// (h0+ty, w0+2tx+1). Single-pass softmax; interleaved K/V pair-block smem
// (word offset = r*1292 + (c>>1)*68 + (c&1)*16 (+32 for V) + d); ehw table.
// ---------------------------------------------------------------------------
#define RSTRIDE 1292             // 19 * 68
#define HROWS 14
#define SM_WORDS (HROWS * RSTRIDE) // 18088 words = 72352 B

__global__ __launch_bounds__(128, 3) void attn_kernel(
    const float* __restrict__ bk, const float* __restrict__ bv,
    const float* __restrict__ pos_h, const float* __restrict__ pos_w,
    float* __restrict__ outp)
{
    extern __shared__ float sm[];
    __shared__ float ehw[52];

    const int tr = blockIdx.x >> 1, tc = blockIdx.x & 1;
    const int h0 = tr * 8, w0 = tc * 32;
    const int nh = blockIdx.y, b = blockIdx.z;
    const int tx = threadIdx.x;   // 0..15
    const int ty = threadIdx.y;   // 0..7
    const int tid = ty * 16 + tx;
    const int cbase = nh * DHh;

    const float* kb = g_k + (size_t)b * CHW + cbase;
    const float* vb = g_v + (size_t)b * CHW + cbase;

    if (tid < 49)
        ehw[tid] = __expf(pos_h[nh * 7 + tid / 7] + pos_w[nh * 7 + tid % 7]);

    // ---- q loads issued before the barrier (overlap with halo fill) ----
    const int h = h0 + ty, w = w0 + 2 * tx;
    const float* qp = g_q + (size_t)b * CHW + (size_t)(h * Ww + w) * Cc + cbase;
    float4 qf0[4], qf1[4];
#pragma unroll
    for (int t = 0; t < 4; t++) {
        qf0[t] = *(const float4*)(qp + t * 4);
        qf1[t] = *(const float4*)(qp + Cc + t * 4);
    }

    // ---- fill halo: 14 x 38 sites x 4 quads (float4), K+V per iter ----
    for (int idx = tid; idx < HROWS * 38 * 4; idx += 128) {
        int quad = idx & 3;
        int site = idx >> 2;
        int r = site / 38, c = site - r * 38;
        int gh = h0 - PADk + r, gw = w0 - PADk + c;
        float4 kq, vq;
        if ((unsigned)gh < (unsigned)Hh && (unsigned)gw < (unsigned)Ww) {
            size_t g = (size_t)(gh * Ww + gw) * Cc + quad * 4;
            kq = *(const float4*)(kb + g);
            vq = *(const float4*)(vb + g);
        } else {
            kq = *(const float4*)(bk + cbase + quad * 4);
            vq = *(const float4*)(bv + cbase + quad * 4);
        }
        int off = r * RSTRIDE + (c >> 1) * 68 + (c & 1) * 16 + quad * 4;
        *(float4*)(sm + off)      = kq;
        *(float4*)(sm + off + 32) = vq;
    }
    __syncthreads();

    ull q0p[8], q1p[8];
#pragma unroll
    for (int t = 0; t < 4; t++) {
        q0p[2 * t]     = pack2(qf0[t].x, qf0[t].y);
        q0p[2 * t + 1] = pack2(qf0[t].z, qf0[t].w);
        q1p[2 * t]     = pack2(qf1[t].x, qf1[t].y);
        q1p[2 * t + 1] = pack2(qf1[t].z, qf1[t].w);
    }

    ull acc0[8], acc1[8];
#pragma unroll
    for (int t = 0; t < 8; t++) { acc0[t] = 0ull; acc1[t] = 0ull; }
    float sum0 = 0.f, sum1 = 0.f;

#pragma unroll 1
    for (int i = 0; i < 7; i++) {
        const float* rowp = sm + (ty + i) * RSTRIDE;
        const float* eh_row = ehw + i * 7;
#pragma unroll
        for (int c = 0; c < 8; c++) {
            const float* p = rowp + (tx + (c >> 1)) * 68 + (c & 1) * 16;
            ulonglong2 kA = ((const ulonglong2*)p)[0];
            ulonglong2 kB = ((const ulonglong2*)p)[1];
            ulonglong2 kC = ((const ulonglong2*)p)[2];
            ulonglong2 kD = ((const ulonglong2*)p)[3];

            float w0e = 0.f, w1e = 0.f;
            if (c < 7) {   // pixel0 neighbor j = c
                ull sA = fma2(q0p[0], kA.x, 0ull);
                ull sB = fma2(q0p[1], kA.y, 0ull);
                sA = fma2(q0p[2], kB.x, sA);
                sB = fma2(q0p[3], kB.y, sB);
                sA = fma2(q0p[4], kC.x, sA);
                sB = fma2(q0p[5], kC.y, sB);
                sA = fma2(q0p[6], kD.x, sA);
                sB = fma2(q0p[7], kD.y, sB);
                float2 f = unpack2(add2(sA, sB));
                w0e = __expf(f.x + f.y) * eh_row[c];
                sum0 += w0e;
            }
            if (c >= 1) {  // pixel1 neighbor j = c-1
                ull sA = fma2(q1p[0], kA.x, 0ull);
                ull sB = fma2(q1p[1], kA.y, 0ull);
                sA = fma2(q1p[2], kB.x, sA);
                sB = fma2(q1p[3], kB.y, sB);
                sA = fma2(q1p[4], kC.x, sA);
                sB = fma2(q1p[5], kC.y, sB);
                sA = fma2(q1p[6], kD.x, sA);
                sB = fma2(q1p[7], kD.y, sB);
                float2 f = unpack2(add2(sA, sB));
                w1e = __expf(f.x + f.y) * eh_row[c - 1];
                sum1 += w1e;
            }

            const float* pv = p + 32;
            ulonglong2 vA = ((const ulonglong2*)pv)[0];
            ulonglong2 vB = ((const ulonglong2*)pv)[1];
            ulonglong2 vC = ((const ulonglong2*)pv)[2];
            ulonglong2 vD = ((const ulonglong2*)pv)[3];

            if (c < 7) {
                ull wp = pack2(w0e, w0e);
                acc0[0] = fma2(wp, vA.x, acc0[0]);
                acc0[1] = fma2(wp, vA.y, acc0[1]);
                acc0[2] = fma2(wp, vB.x, acc0[2]);
                acc0[3] = fma2(wp, vB.y, acc0[3]);
                acc0[4] = fma2(wp, vC.x, acc0[4]);
                acc0[5] = fma2(wp, vC.y, acc0[5]);
                acc0[6] = fma2(wp, vD.x, acc0[6]);
                acc0[7] = fma2(wp, vD.y, acc0[7]);
            }
            if (c >= 1) {
                ull wp = pack2(w1e, w1e);
                acc1[0] = fma2(wp, vA.x, acc1[0]);
                acc1[1] = fma2(wp, vA.y, acc1[1]);
                acc1[2] = fma2(wp, vB.x, acc1[2]);
                acc1[3] = fma2(wp, vB.y, acc1[3]);
                acc1[4] = fma2(wp, vC.x, acc1[4]);
                acc1[5] = fma2(wp, vC.y, acc1[5]);
                acc1[6] = fma2(wp, vD.x, acc1[6]);
                acc1[7] = fma2(wp, vD.y, acc1[7]);
            }
        }
    }

    const float inv0 = __fdividef(1.f, sum0);
    const float inv1 = __fdividef(1.f, sum1);

    float* op = outp + ((size_t)(b * Cc + cbase) * Hh + h) * Ww + w;
#pragma unroll
    for (int t = 0; t < 8; t++) {
        float2 a0 = unpack2(acc0[t]);
        float2 a1 = unpack2(acc1[t]);
        float2 olo = make_float2(a0.x * inv0, a1.x * inv1);
        float2 ohi = make_float2(a0.y * inv0, a1.y * inv1);
        *(float2*)(op + (2 * t) * HW)     = olo;
        *(float2*)(op + (2 * t + 1) * HW) = ohi;
    }
}

// ---------------------------------------------------------------------------
extern "C" void kernel_launch(void* const* d_in, const int* in_sizes, int n_in,
                              void* d_out, int out_size) {
    const float* x  = (const float*)d_in[0];
    const float* wq = (const float*)d_in[1];
    const float* bq = (const float*)d_in[2];
    const float* wk = (const float*)d_in[3];
    const float* bk = (const float*)d_in[4];
    const float* wv = (const float*)d_in[5];
    const float* bv = (const float*)d_in[6];
    const float* ph = (const float*)d_in[7];
    const float* pw = (const float*)d_in[8];
    float* out = (float*)d_out;

    cudaFuncSetAttribute((const void*)qkv_hmma,
                         cudaFuncAttributeMaxDynamicSharedMemorySize, GEMM_SMEM);
    const size_t attn_smem = SM_WORDS * sizeof(float);  // 72352
    cudaFuncSetAttribute((const void*)attn_kernel,
                         cudaFuncAttributeMaxDynamicSharedMemorySize, (int)attn_smem);

    wpack_kernel<<<48, 256>>>(wq, wk, wv);
    qkv_hmma<<<256, 256, GEMM_SMEM>>>(x, bq, bk, bv);
    attn_kernel<<<dim3(16, NHh, Bsz), dim3(16, 8), attn_smem>>>(bk, bv, ph, pw, out);
}

// round 12
// speedup vs baseline: 1.1171x; 1.1171x over previous
#include <cuda_runtime.h>
#include <cuda_bf16.h>
#include <cstdint>

#define Bsz 4
#define Cc  128
#define Hh  64
#define Ww  64
#define Kk  7
#define NHh 8
#define DHh 16
#define PADk 3
#define HW  (Hh*Ww)        // 4096
#define CHW (Cc*HW)        // 524288

typedef unsigned long long ull;

// scratch for projections, CHANNEL-LAST layout [b][hw][c]
__device__ float g_q[Bsz*CHW];
__device__ float g_k[Bsz*CHW];
__device__ float g_v[Bsz*CHW];

#define LDK 136                          // padded bf16 row length (272 B)
#define WIMG (128 * LDK)                 // ushorts per image (17408)
// pre-packed W: [proj][hi|lo] images in the exact smem layout
__device__ unsigned short g_wpack[3 * 2 * WIMG];

// ---------------- packed f32x2 helpers ----------------
__device__ __forceinline__ ull fma2(ull a, ull b, ull c) {
    ull d; asm("fma.rn.f32x2 %0, %1, %2, %3;" : "=l"(d) : "l"(a), "l"(b), "l"(c)); return d;
}
__device__ __forceinline__ ull add2(ull a, ull b) {
    ull d; asm("add.rn.f32x2 %0, %1, %2;" : "=l"(d) : "l"(a), "l"(b)); return d;
}
__device__ __forceinline__ ull pack2(float lo, float hi) {
    ull d; asm("mov.b64 %0, {%1, %2};" : "=l"(d) : "f"(lo), "f"(hi)); return d;
}
__device__ __forceinline__ float2 unpack2(ull v) {
    float2 r; asm("mov.b64 {%0, %1}, %2;" : "=f"(r.x), "=f"(r.y) : "l"(v)); return r;
}

// ---------------- HMMA helpers (sm_80+) ----------------
__device__ __forceinline__ uint32_t smem_u32(const void* p) {
    uint32_t a;
    asm("{ .reg .u64 t; cvta.to.shared.u64 t, %1; cvt.u32.u64 %0, t; }" : "=r"(a) : "l"(p));
    return a;
}
__device__ __forceinline__ void ldsm_x4(uint32_t& r0, uint32_t& r1, uint32_t& r2,
                                        uint32_t& r3, uint32_t addr) {
    asm volatile("ldmatrix.sync.aligned.m8n8.x4.shared.b16 {%0,%1,%2,%3}, [%4];"
                 : "=r"(r0), "=r"(r1), "=r"(r2), "=r"(r3) : "r"(addr));
}
__device__ __forceinline__ void mma_bf16(float* c, const uint32_t* a, const uint32_t* b) {
    asm volatile(
        "mma.sync.aligned.m16n8k16.row.col.f32.bf16.bf16.f32 "
        "{%0,%1,%2,%3}, {%4,%5,%6,%7}, {%8,%9}, {%0,%1,%2,%3};"
        : "+f"(c[0]), "+f"(c[1]), "+f"(c[2]), "+f"(c[3])
        : "r"(a[0]), "r"(a[1]), "r"(a[2]), "r"(a[3]), "r"(b[0]), "r"(b[1]));
}

// ---------------------------------------------------------------------------
// Kernel 0: pack W fp32 -> bf16 hi/lo images.  Grid = 48.
// ---------------------------------------------------------------------------
__global__ void wpack_kernel(const float* __restrict__ wq,
                             const float* __restrict__ wk,
                             const float* __restrict__ wv) {
    const int proj  = blockIdx.x >> 4;
    const int chunk = blockIdx.x & 15;
    const float* W = (proj == 0) ? wq : (proj == 1) ? wk : wv;
    unsigned short* hi = g_wpack + proj * 2 * WIMG;
    unsigned short* lo = hi + WIMG;
    int e = chunk * 1024 + threadIdx.x * 4;
    int m = e >> 7, c = e & 127;
    float4 v4 = *(const float4*)&W[e];
    ushort4 h4, l4;
    __nv_bfloat16 h;
    h = __float2bfloat16(v4.x); h4.x = __bfloat16_as_ushort(h);
    l4.x = __bfloat16_as_ushort(__float2bfloat16(v4.x - __bfloat162float(h)));
    h = __float2bfloat16(v4.y); h4.y = __bfloat16_as_ushort(h);
    l4.y = __bfloat16_as_ushort(__float2bfloat16(v4.y - __bfloat162float(h)));
    h = __float2bfloat16(v4.z); h4.z = __bfloat16_as_ushort(h);
    l4.z = __bfloat16_as_ushort(__float2bfloat16(v4.z - __bfloat162float(h)));
    h = __float2bfloat16(v4.w); h4.w = __bfloat16_as_ushort(h);
    l4.w = __bfloat16_as_ushort(__float2bfloat16(v4.w - __bfloat162float(h)));
    *(ushort4*)&hi[m * LDK + c] = h4;
    *(ushort4*)&lo[m * LDK + c] = l4;
}

// ---------------------------------------------------------------------------
// Kernel 1 (R9, proven ~10.4us): fused QKV GEMM via HMMA (bf16 hi/lo).
// Grid = 256 (64 px each, 2 blocks/SM). 8 warps (4m x 2n), warp tile 32x32.
// ---------------------------------------------------------------------------
#define XHI_OFF 0
#define XLO_OFF (64 * LDK * 2)          // 17408
#define WHI_OFF (2 * 64 * LDK * 2)      // 34816
#define WLO_OFF (WHI_OFF + 128 * LDK * 2)
#define GEMM_SMEM (WHI_OFF + 2 * 128 * LDK * 2)   // 104448 B

__global__ __launch_bounds__(256, 2) void qkv_hmma(
    const float* __restrict__ x,
    const float* __restrict__ bq, const float* __restrict__ bk,
    const float* __restrict__ bv)
{
    extern __shared__ char smc[];
    unsigned short* Xhi = (unsigned short*)(smc + XHI_OFF);
    unsigned short* Xlo = (unsigned short*)(smc + XLO_OFF);
    const uint32_t sb = smem_u32(smc);

    const int tid = threadIdx.x;
    const int warp = tid >> 5, lane = tid & 31;
    const int wy = warp >> 1, wx = warp & 1;   // m = wy*32, n = wx*32
    const int n0 = blockIdx.x * 64;
    const int b = n0 >> 12, hw0 = n0 & 4095;
    const float* xb = x + (size_t)b * CHW + hw0;

    // ---- X tile (64 px): fp32 -> bf16 hi/lo, [n][k] ----
    for (int e = tid; e < 8192; e += 256) {
        int c = e >> 6, n = e & 63;
        float v = xb[c * HW + n];
        __nv_bfloat16 h = __float2bfloat16(v);
        __nv_bfloat16 l = __float2bfloat16(v - __bfloat162float(h));
        Xhi[n * LDK + c] = __bfloat16_as_ushort(h);
        Xlo[n * LDK + c] = __bfloat16_as_ushort(l);
    }

#pragma unroll 1
    for (int p = 0; p < 3; p++) {
        const float* bp = (p == 0) ? bq : (p == 1) ? bk : bv;
        float* og = ((p == 0) ? g_q : (p == 1) ? g_k : g_v) + (size_t)n0 * 128;

        __syncthreads();   // X ready (p=0); prior mma reads of W done (p>0)
        // ---- copy W(p) hi+lo images (69632 B, pure float4 copy) ----
        {
            const float4* src = (const float4*)(g_wpack + p * 2 * WIMG);
            float4* dst = (float4*)(smc + WHI_OFF);
#pragma unroll
            for (int i = 0; i < 17; i++) dst[tid + i * 256] = src[tid + i * 256];
        }
        __syncthreads();

        float acc[2][4][4];
#pragma unroll
        for (int i = 0; i < 2; i++)
#pragma unroll
            for (int j = 0; j < 4; j++)
#pragma unroll
                for (int t = 0; t < 4; t++) acc[i][j][t] = 0.f;

#pragma unroll
        for (int k = 0; k < 8; k++) {
            const int kb = k * 16;
            uint32_t ahi[2][4], alo[2][4];
#pragma unroll
            for (int mf = 0; mf < 2; mf++) {
                int row = wy * 32 + mf * 16 + (lane & 15);
                int col = kb + ((lane >> 4) << 3);
                uint32_t off = (uint32_t)(row * LDK + col) * 2;
                ldsm_x4(ahi[mf][0], ahi[mf][1], ahi[mf][2], ahi[mf][3],
                        sb + WHI_OFF + off);
                ldsm_x4(alo[mf][0], alo[mf][1], alo[mf][2], alo[mf][3],
                        sb + WLO_OFF + off);
            }
            uint32_t bhi[4][2], blo[4][2];
#pragma unroll
            for (int nf4 = 0; nf4 < 2; nf4++) {
                int g = lane >> 3;
                int row = wx * 32 + nf4 * 16 + (lane & 7) + ((g & 2) << 2);
                int col = kb + ((g & 1) << 3);
                uint32_t off = (uint32_t)(row * LDK + col) * 2;
                uint32_t r0, r1, r2, r3;
                ldsm_x4(r0, r1, r2, r3, sb + XHI_OFF + off);
                bhi[nf4 * 2][0] = r0; bhi[nf4 * 2][1] = r1;
                bhi[nf4 * 2 + 1][0] = r2; bhi[nf4 * 2 + 1][1] = r3;
                ldsm_x4(r0, r1, r2, r3, sb + XLO_OFF + off);
                blo[nf4 * 2][0] = r0; blo[nf4 * 2][1] = r1;
                blo[nf4 * 2 + 1][0] = r2; blo[nf4 * 2 + 1][1] = r3;
            }
#pragma unroll
            for (int mf = 0; mf < 2; mf++)
#pragma unroll
                for (int nf = 0; nf < 4; nf++) {
                    mma_bf16(acc[mf][nf], ahi[mf], bhi[nf]);
                    mma_bf16(acc[mf][nf], ahi[mf], blo[nf]);
                    mma_bf16(acc[mf][nf], alo[mf], bhi[nf]);
                }
        }

        // ---- epilogue: channel-last store ----
#pragma unroll
        for (int mf = 0; mf < 2; mf++) {
            int r0 = wy * 32 + mf * 16 + (lane >> 2);
            int r1 = r0 + 8;
            float bi0 = bp[r0], bi1 = bp[r1];
#pragma unroll
            for (int nf = 0; nf < 4; nf++) {
                int c0 = wx * 32 + nf * 8 + (lane & 3) * 2;
                float* o0 = og + (size_t)c0 * 128;
                float* o1 = o0 + 128;
                o0[r0] = acc[mf][nf][0] + bi0;
                o1[r0] = acc[mf][nf][1] + bi0;
                o0[r1] = acc[mf][nf][2] + bi1;
                o1[r1] = acc[mf][nf][3] + bi1;
            }
        }
    }
}

// ---------------------------------------------------------------------------
// Kernel 2: local attention (R6-exact, proven 33.3us) + warp-staggered loop
// entry to break the post-barrier LDS convoy. 16x32 tile, 2 px/thread,
// single-pass softmax, interleaved K/V pair-block smem, ehw table.
// ---------------------------------------------------------------------------
#define RSTRIDE 1292             // 19 * 68
#define HROWS 22
#define SM_WORDS (HROWS * RSTRIDE) // 113696 B

__global__ __launch_bounds__(256, 2) void attn_kernel(
    const float* __restrict__ bk, const float* __restrict__ bv,
    const float* __restrict__ pos_h, const float* __restrict__ pos_w,
    float* __restrict__ outp)
{
    extern __shared__ float sm[];
    __shared__ float ehw[52];

    const int tr = blockIdx.x >> 1, tc = blockIdx.x & 1;
    const int h0 = tr * 16, w0 = tc * 32;
    const int nh = blockIdx.y, b = blockIdx.z;
    const int tx = threadIdx.x, ty = threadIdx.y;
    const int tid = ty * 16 + tx;
    const int cbase = nh * DHh;

    const float* kb = g_k + (size_t)b * CHW + cbase;
    const float* vb = g_v + (size_t)b * CHW + cbase;

    if (tid < 49)
        ehw[tid] = __expf(pos_h[nh * 7 + tid / 7] + pos_w[nh * 7 + tid % 7]);

    // ---- q loads issued before the barrier (overlap with halo fill) ----
    const int h = h0 + ty, w = w0 + 2 * tx;
    const float* qp = g_q + (size_t)b * CHW + (size_t)(h * Ww + w) * Cc + cbase;
    float4 qf0[4], qf1[4];
#pragma unroll
    for (int t = 0; t < 4; t++) {
        qf0[t] = *(const float4*)(qp + t * 4);
        qf1[t] = *(const float4*)(qp + Cc + t * 4);
    }

    // ---- fill halo: 22 x 38 sites x 4 quads (float4), K+V per iter ----
    for (int idx = tid; idx < HROWS * 38 * 4; idx += 256) {
        int quad = idx & 3;
        int site = idx >> 2;
        int r = site / 38, c = site - r * 38;
        int gh = h0 - PADk + r, gw = w0 - PADk + c;
        float4 kq, vq;
        if ((unsigned)gh < (unsigned)Hh && (unsigned)gw < (unsigned)Ww) {
            size_t g = (size_t)(gh * Ww + gw) * Cc + quad * 4;
            kq = *(const float4*)(kb + g);
            vq = *(const float4*)(vb + g);
        } else {
            kq = *(const float4*)(bk + cbase + quad * 4);
            vq = *(const float4*)(bv + cbase + quad * 4);
        }
        int off = r * RSTRIDE + (c >> 1) * 68 + (c & 1) * 16 + quad * 4;
        *(float4*)(sm + off)      = kq;
        *(float4*)(sm + off + 32) = vq;
    }
    __syncthreads();

    // ---- convoy breaker: stagger each warp's entry into the main loop ----
    __nanosleep((tid >> 5) * 40);

    ull q0p[8], q1p[8];
#pragma unroll
    for (int t = 0; t < 4; t++) {
        q0p[2 * t]     = pack2(qf0[t].x, qf0[t].y);
        q0p[2 * t + 1] = pack2(qf0[t].z, qf0[t].w);
        q1p[2 * t]     = pack2(qf1[t].x, qf1[t].y);
        q1p[2 * t + 1] = pack2(qf1[t].z, qf1[t].w);
    }

    ull acc0[8], acc1[8];
#pragma unroll
    for (int t = 0; t < 8; t++) { acc0[t] = 0ull; acc1[t] = 0ull; }
    float sum0 = 0.f, sum1 = 0.f;

#pragma unroll 1
    for (int i = 0; i < 7; i++) {
        const float* rowp = sm + (ty + i) * RSTRIDE;
        const float* eh_row = ehw + i * 7;
#pragma unroll
        for (int c = 0; c < 8; c++) {
            const float* p = rowp + (tx + (c >> 1)) * 68 + (c & 1) * 16;
            ulonglong2 kA = ((const ulonglong2*)p)[0];
            ulonglong2 kB = ((const ulonglong2*)p)[1];
            ulonglong2 kC = ((const ulonglong2*)p)[2];
            ulonglong2 kD = ((const ulonglong2*)p)[3];

            float w0e = 0.f, w1e = 0.f;
            if (c < 7) {
                ull sA = fma2(q0p[0], kA.x, 0ull);
                ull sB = fma2(q0p[1], kA.y, 0ull);
                sA = fma2(q0p[2], kB.x, sA);
                sB = fma2(q0p[3], kB.y, sB);
                sA = fma2(q0p[4], kC.x, sA);
                sB = fma2(q0p[5], kC.y, sB);
                sA = fma2(q0p[6], kD.x, sA);
                sB = fma2(q0p[7], kD.y, sB);
                float2 f = unpack2(add2(sA, sB));
                w0e = __expf(f.x + f.y) * eh_row[c];
                sum0 += w0e;
            }
            if (c >= 1) {
                ull sA = fma2(q1p[0], kA.x, 0ull);
                ull sB = fma2(q1p[1], kA.y, 0ull);
                sA = fma2(q1p[2], kB.x, sA);
                sB = fma2(q1p[3], kB.y, sB);
                sA = fma2(q1p[4], kC.x, sA);
                sB = fma2(q1p[5], kC.y, sB);
                sA = fma2(q1p[6], kD.x, sA);
                sB = fma2(q1p[7], kD.y, sB);
                float2 f = unpack2(add2(sA, sB));
                w1e = __expf(f.x + f.y) * eh_row[c - 1];
                sum1 += w1e;
            }

            const float* pv = p + 32;
            ulonglong2 vA = ((const ulonglong2*)pv)[0];
            ulonglong2 vB = ((const ulonglong2*)pv)[1];
            ulonglong2 vC = ((const ulonglong2*)pv)[2];
            ulonglong2 vD = ((const ulonglong2*)pv)[3];

            if (c < 7) {
                ull wp = pack2(w0e, w0e);
                acc0[0] = fma2(wp, vA.x, acc0[0]);
                acc0[1] = fma2(wp, vA.y, acc0[1]);
                acc0[2] = fma2(wp, vB.x, acc0[2]);
                acc0[3] = fma2(wp, vB.y, acc0[3]);
                acc0[4] = fma2(wp, vC.x, acc0[4]);
                acc0[5] = fma2(wp, vC.y, acc0[5]);
                acc0[6] = fma2(wp, vD.x, acc0[6]);
                acc0[7] = fma2(wp, vD.y, acc0[7]);
            }
            if (c >= 1) {
                ull wp = pack2(w1e, w1e);
                acc1[0] = fma2(wp, vA.x, acc1[0]);
                acc1[1] = fma2(wp, vA.y, acc1[1]);
                acc1[2] = fma2(wp, vB.x, acc1[2]);
                acc1[3] = fma2(wp, vB.y, acc1[3]);
                acc1[4] = fma2(wp, vC.x, acc1[4]);
                acc1[5] = fma2(wp, vC.y, acc1[5]);
                acc1[6] = fma2(wp, vD.x, acc1[6]);
                acc1[7] = fma2(wp, vD.y, acc1[7]);
            }
        }
    }

    const float inv0 = __fdividef(1.f, sum0);
    const float inv1 = __fdividef(1.f, sum1);

    float* op = outp + ((size_t)(b * Cc + cbase) * Hh + h) * Ww + w;
#pragma unroll
    for (int t = 0; t < 8; t++) {
        float2 a0 = unpack2(acc0[t]);
        float2 a1 = unpack2(acc1[t]);
        float2 olo = make_float2(a0.x * inv0, a1.x * inv1);
        float2 ohi = make_float2(a0.y * inv0, a1.y * inv1);
        *(float2*)(op + (2 * t) * HW)     = olo;
        *(float2*)(op + (2 * t + 1) * HW) = ohi;
    }
}

// ---------------------------------------------------------------------------
extern "C" void kernel_launch(void* const* d_in, const int* in_sizes, int n_in,
                              void* d_out, int out_size) {
    const float* x  = (const float*)d_in[0];
    const float* wq = (const float*)d_in[1];
    const float* bq = (const float*)d_in[2];
    const float* wk = (const float*)d_in[3];
    const float* bk = (const float*)d_in[4];
    const float* wv = (const float*)d_in[5];
    const float* bv = (const float*)d_in[6];
    const float* ph = (const float*)d_in[7];
    const float* pw = (const float*)d_in[8];
    float* out = (float*)d_out;

    cudaFuncSetAttribute((const void*)qkv_hmma,
                         cudaFuncAttributeMaxDynamicSharedMemorySize, GEMM_SMEM);
    const size_t attn_smem = SM_WORDS * sizeof(float);  // 113696
    cudaFuncSetAttribute((const void*)attn_kernel,
                         cudaFuncAttributeMaxDynamicSharedMemorySize, (int)attn_smem);

    wpack_kernel<<<48, 256>>>(wq, wk, wv);
    qkv_hmma<<<256, 256, GEMM_SMEM>>>(x, bq, bk, bv);
    attn_kernel<<<dim3(8, NHh, Bsz), dim3(16, 16), attn_smem>>>(bk, bv, ph, pw, out);
}

// round 13
// speedup vs baseline: 1.1501x; 1.0295x over previous
#include <cuda_runtime.h>
#include <cuda_bf16.h>
#include <cstdint>

#define Bsz 4
#define Cc  128
#define Hh  64
#define Ww  64
#define Kk  7
#define NHh 8
#define DHh 16
#define PADk 3
#define HW  (Hh*Ww)        // 4096
#define CHW (Cc*HW)        // 524288

typedef unsigned long long ull;

// scratch for projections, CHANNEL-LAST layout [b][hw][c]
__device__ float g_q[Bsz*CHW];
__device__ float g_k[Bsz*CHW];
__device__ float g_v[Bsz*CHW];

#define LDK 136                          // padded bf16 row length (272 B)

// ---------------- packed f32x2 helpers ----------------
__device__ __forceinline__ ull fma2(ull a, ull b, ull c) {
    ull d; asm("fma.rn.f32x2 %0, %1, %2, %3;" : "=l"(d) : "l"(a), "l"(b), "l"(c)); return d;
}
__device__ __forceinline__ ull add2(ull a, ull b) {
    ull d; asm("add.rn.f32x2 %0, %1, %2;" : "=l"(d) : "l"(a), "l"(b)); return d;
}
__device__ __forceinline__ ull pack2(float lo, float hi) {
    ull d; asm("mov.b64 %0, {%1, %2};" : "=l"(d) : "f"(lo), "f"(hi)); return d;
}
__device__ __forceinline__ float2 unpack2(ull v) {
    float2 r; asm("mov.b64 {%0, %1}, %2;" : "=f"(r.x), "=f"(r.y) : "l"(v)); return r;
}

// ---------------- HMMA helpers (sm_80+) ----------------
__device__ __forceinline__ uint32_t smem_u32(const void* p) {
    uint32_t a;
    asm("{ .reg .u64 t; cvta.to.shared.u64 t, %1; cvt.u32.u64 %0, t; }" : "=r"(a) : "l"(p));
    return a;
}
__device__ __forceinline__ void ldsm_x4(uint32_t& r0, uint32_t& r1, uint32_t& r2,
                                        uint32_t& r3, uint32_t addr) {
    asm volatile("ldmatrix.sync.aligned.m8n8.x4.shared.b16 {%0,%1,%2,%3}, [%4];"
                 : "=r"(r0), "=r"(r1), "=r"(r2), "=r"(r3) : "r"(addr));
}
__device__ __forceinline__ void mma_bf16(float* c, const uint32_t* a, const uint32_t* b) {
    asm volatile(
        "mma.sync.aligned.m16n8k16.row.col.f32.bf16.bf16.f32 "
        "{%0,%1,%2,%3}, {%4,%5,%6,%7}, {%8,%9}, {%0,%1,%2,%3};"
        : "+f"(c[0]), "+f"(c[1]), "+f"(c[2]), "+f"(c[3])
        : "r"(a[0]), "r"(a[1]), "r"(a[2]), "r"(a[3]), "r"(b[0]), "r"(b[1]));
}

// ---------------------------------------------------------------------------
// Kernel 1: fused QKV GEMM via HMMA (bf16 hi/lo, 3 terms), W converted
// in-block (wpack kernel eliminated — its 4.5us was pure launch floor).
// Grid = 256 (64 px each, 2 blocks/SM). 8 warps (4m x 2n), warp tile 32x32.
// ---------------------------------------------------------------------------
#define XHI_OFF 0
#define XLO_OFF (64 * LDK * 2)          // 17408
#define WHI_OFF (2 * 64 * LDK * 2)      // 34816
#define WLO_OFF (WHI_OFF + 128 * LDK * 2)
#define GEMM_SMEM (WHI_OFF + 2 * 128 * LDK * 2)   // 104448 B

__global__ __launch_bounds__(256, 2) void qkv_hmma(
    const float* __restrict__ x,
    const float* __restrict__ wq, const float* __restrict__ bq,
    const float* __restrict__ wk, const float* __restrict__ bk,
    const float* __restrict__ wv, const float* __restrict__ bv)
{
    extern __shared__ char smc[];
    unsigned short* Xhi = (unsigned short*)(smc + XHI_OFF);
    unsigned short* Xlo = (unsigned short*)(smc + XLO_OFF);
    unsigned short* Whi = (unsigned short*)(smc + WHI_OFF);
    unsigned short* Wlo = (unsigned short*)(smc + WLO_OFF);
    const uint32_t sb = smem_u32(smc);

    const int tid = threadIdx.x;
    const int warp = tid >> 5, lane = tid & 31;
    const int wy = warp >> 1, wx = warp & 1;   // m = wy*32, n = wx*32
    const int n0 = blockIdx.x * 64;
    const int b = n0 >> 12, hw0 = n0 & 4095;
    const float* xb = x + (size_t)b * CHW + hw0;

    // ---- X tile (64 px): fp32 -> bf16 hi/lo, [n][k] ----
    for (int e = tid; e < 8192; e += 256) {
        int c = e >> 6, n = e & 63;
        float v = xb[c * HW + n];
        __nv_bfloat16 h = __float2bfloat16(v);
        __nv_bfloat16 l = __float2bfloat16(v - __bfloat162float(h));
        Xhi[n * LDK + c] = __bfloat16_as_ushort(h);
        Xlo[n * LDK + c] = __bfloat16_as_ushort(l);
    }

#pragma unroll 1
    for (int p = 0; p < 3; p++) {
        const float* Wp = (p == 0) ? wq : (p == 1) ? wk : wv;
        const float* bp = (p == 0) ? bq : (p == 1) ? bk : bv;
        float* og = ((p == 0) ? g_q : (p == 1) ? g_k : g_v) + (size_t)n0 * 128;

        __syncthreads();   // X ready (p=0); prior mma reads of W done (p>0)
        // ---- convert W(p) fp32 -> bf16 hi/lo into smem (coalesced) ----
        for (int e = tid * 4; e < 16384; e += 1024) {
            int m = e >> 7, c = e & 127;
            float4 v4 = *(const float4*)&Wp[e];
            ushort4 h4, l4;
            __nv_bfloat16 h;
            h = __float2bfloat16(v4.x); h4.x = __bfloat16_as_ushort(h);
            l4.x = __bfloat16_as_ushort(__float2bfloat16(v4.x - __bfloat162float(h)));
            h = __float2bfloat16(v4.y); h4.y = __bfloat16_as_ushort(h);
            l4.y = __bfloat16_as_ushort(__float2bfloat16(v4.y - __bfloat162float(h)));
            h = __float2bfloat16(v4.z); h4.z = __bfloat16_as_ushort(h);
            l4.z = __bfloat16_as_ushort(__float2bfloat16(v4.z - __bfloat162float(h)));
            h = __float2bfloat16(v4.w); h4.w = __bfloat16_as_ushort(h);
            l4.w = __bfloat16_as_ushort(__float2bfloat16(v4.w - __bfloat162float(h)));
            *(ushort4*)&Whi[m * LDK + c] = h4;
            *(ushort4*)&Wlo[m * LDK + c] = l4;
        }
        __syncthreads();

        float acc[2][4][4];
#pragma unroll
        for (int i = 0; i < 2; i++)
#pragma unroll
            for (int j = 0; j < 4; j++)
#pragma unroll
                for (int t = 0; t < 4; t++) acc[i][j][t] = 0.f;

#pragma unroll
        for (int k = 0; k < 8; k++) {
            const int kb = k * 16;
            uint32_t ahi[2][4], alo[2][4];
#pragma unroll
            for (int mf = 0; mf < 2; mf++) {
                int row = wy * 32 + mf * 16 + (lane & 15);
                int col = kb + ((lane >> 4) << 3);
                uint32_t off = (uint32_t)(row * LDK + col) * 2;
                ldsm_x4(ahi[mf][0], ahi[mf][1], ahi[mf][2], ahi[mf][3],
                        sb + WHI_OFF + off);
                ldsm_x4(alo[mf][0], alo[mf][1], alo[mf][2], alo[mf][3],
                        sb + WLO_OFF + off);
            }
            uint32_t bhi[4][2], blo[4][2];
#pragma unroll
            for (int nf4 = 0; nf4 < 2; nf4++) {
                int g = lane >> 3;
                int row = wx * 32 + nf4 * 16 + (lane & 7) + ((g & 2) << 2);
                int col = kb + ((g & 1) << 3);
                uint32_t off = (uint32_t)(row * LDK + col) * 2;
                uint32_t r0, r1, r2, r3;
                ldsm_x4(r0, r1, r2, r3, sb + XHI_OFF + off);
                bhi[nf4 * 2][0] = r0; bhi[nf4 * 2][1] = r1;
                bhi[nf4 * 2 + 1][0] = r2; bhi[nf4 * 2 + 1][1] = r3;
                ldsm_x4(r0, r1, r2, r3, sb + XLO_OFF + off);
                blo[nf4 * 2][0] = r0; blo[nf4 * 2][1] = r1;
                blo[nf4 * 2 + 1][0] = r2; blo[nf4 * 2 + 1][1] = r3;
            }
#pragma unroll
            for (int mf = 0; mf < 2; mf++)
#pragma unroll
                for (int nf = 0; nf < 4; nf++) {
                    mma_bf16(acc[mf][nf], ahi[mf], bhi[nf]);
                    mma_bf16(acc[mf][nf], ahi[mf], blo[nf]);
                    mma_bf16(acc[mf][nf], alo[mf], bhi[nf]);
                }
        }

        // ---- epilogue: channel-last store ----
#pragma unroll
        for (int mf = 0; mf < 2; mf++) {
            int r0 = wy * 32 + mf * 16 + (lane >> 2);
            int r1 = r0 + 8;
            float bi0 = bp[r0], bi1 = bp[r1];
#pragma unroll
            for (int nf = 0; nf < 4; nf++) {
                int c0 = wx * 32 + nf * 8 + (lane & 3) * 2;
                float* o0 = og + (size_t)c0 * 128;
                float* o1 = o0 + 128;
                o0[r0] = acc[mf][nf][0] + bi0;
                o1[r0] = acc[mf][nf][1] + bi0;
                o0[r1] = acc[mf][nf][2] + bi1;
                o1[r1] = acc[mf][nf][3] + bi1;
            }
        }
    }
}

// ---------------------------------------------------------------------------
// Kernel 2: local attention (R12-exact, proven 33.3us / best total 51.4).
// 16x32 tile, 2 px/thread, single-pass softmax, interleaved K/V pair-block
// smem, ehw table, warp-staggered loop entry.
// ---------------------------------------------------------------------------
#define RSTRIDE 1292             // 19 * 68
#define HROWS 22
#define SM_WORDS (HROWS * RSTRIDE) // 113696 B

__global__ __launch_bounds__(256, 2) void attn_kernel(
    const float* __restrict__ bk, const float* __restrict__ bv,
    const float* __restrict__ pos_h, const float* __restrict__ pos_w,
    float* __restrict__ outp)
{
    extern __shared__ float sm[];
    __shared__ float ehw[52];

    const int tr = blockIdx.x >> 1, tc = blockIdx.x & 1;
    const int h0 = tr * 16, w0 = tc * 32;
    const int nh = blockIdx.y, b = blockIdx.z;
    const int tx = threadIdx.x, ty = threadIdx.y;
    const int tid = ty * 16 + tx;
    const int cbase = nh * DHh;

    const float* kb = g_k + (size_t)b * CHW + cbase;
    const float* vb = g_v + (size_t)b * CHW + cbase;

    if (tid < 49)
        ehw[tid] = __expf(pos_h[nh * 7 + tid / 7] + pos_w[nh * 7 + tid % 7]);

    // ---- q loads issued before the barrier (overlap with halo fill) ----
    const int h = h0 + ty, w = w0 + 2 * tx;
    const float* qp = g_q + (size_t)b * CHW + (size_t)(h * Ww + w) * Cc + cbase;
    float4 qf0[4], qf1[4];
#pragma unroll
    for (int t = 0; t < 4; t++) {
        qf0[t] = *(const float4*)(qp + t * 4);
        qf1[t] = *(const float4*)(qp + Cc + t * 4);
    }

    // ---- fill halo: 22 x 38 sites x 4 quads (float4), K+V per iter ----
    for (int idx = tid; idx < HROWS * 38 * 4; idx += 256) {
        int quad = idx & 3;
        int site = idx >> 2;
        int r = site / 38, c = site - r * 38;
        int gh = h0 - PADk + r, gw = w0 - PADk + c;
        float4 kq, vq;
        if ((unsigned)gh < (unsigned)Hh && (unsigned)gw < (unsigned)Ww) {
            size_t g = (size_t)(gh * Ww + gw) * Cc + quad * 4;
            kq = *(const float4*)(kb + g);
            vq = *(const float4*)(vb + g);
        } else {
            kq = *(const float4*)(bk + cbase + quad * 4);
            vq = *(const float4*)(bv + cbase + quad * 4);
        }
        int off = r * RSTRIDE + (c >> 1) * 68 + (c & 1) * 16 + quad * 4;
        *(float4*)(sm + off)      = kq;
        *(float4*)(sm + off + 32) = vq;
    }
    __syncthreads();

    // ---- stagger each warp's entry into the main loop ----
    __nanosleep((tid >> 5) * 40);

    ull q0p[8], q1p[8];
#pragma unroll
    for (int t = 0; t < 4; t++) {
        q0p[2 * t]     = pack2(qf0[t].x, qf0[t].y);
        q0p[2 * t + 1] = pack2(qf0[t].z, qf0[t].w);
        q1p[2 * t]     = pack2(qf1[t].x, qf1[t].y);
        q1p[2 * t + 1] = pack2(qf1[t].z, qf1[t].w);
    }

    ull acc0[8], acc1[8];
#pragma unroll
    for (int t = 0; t < 8; t++) { acc0[t] = 0ull; acc1[t] = 0ull; }
    float sum0 = 0.f, sum1 = 0.f;

#pragma unroll 1
    for (int i = 0; i < 7; i++) {
        const float* rowp = sm + (ty + i) * RSTRIDE;
        const float* eh_row = ehw + i * 7;
#pragma unroll
        for (int c = 0; c < 8; c++) {
            const float* p = rowp + (tx + (c >> 1)) * 68 + (c & 1) * 16;
            ulonglong2 kA = ((const ulonglong2*)p)[0];
            ulonglong2 kB = ((const ulonglong2*)p)[1];
            ulonglong2 kC = ((const ulonglong2*)p)[2];
            ulonglong2 kD = ((const ulonglong2*)p)[3];

            float w0e = 0.f, w1e = 0.f;
            if (c < 7) {
                ull sA = fma2(q0p[0], kA.x, 0ull);
                ull sB = fma2(q0p[1], kA.y, 0ull);
                sA = fma2(q0p[2], kB.x, sA);
                sB = fma2(q0p[3], kB.y, sB);
                sA = fma2(q0p[4], kC.x, sA);
                sB = fma2(q0p[5], kC.y, sB);
                sA = fma2(q0p[6], kD.x, sA);
                sB = fma2(q0p[7], kD.y, sB);
                float2 f = unpack2(add2(sA, sB));
                w0e = __expf(f.x + f.y) * eh_row[c];
                sum0 += w0e;
            }
            if (c >= 1) {
                ull sA = fma2(q1p[0], kA.x, 0ull);
                ull sB = fma2(q1p[1], kA.y, 0ull);
                sA = fma2(q1p[2], kB.x, sA);
                sB = fma2(q1p[3], kB.y, sB);
                sA = fma2(q1p[4], kC.x, sA);
                sB = fma2(q1p[5], kC.y, sB);
                sA = fma2(q1p[6], kD.x, sA);
                sB = fma2(q1p[7], kD.y, sB);
                float2 f = unpack2(add2(sA, sB));
                w1e = __expf(f.x + f.y) * eh_row[c - 1];
                sum1 += w1e;
            }

            const float* pv = p + 32;
            ulonglong2 vA = ((const ulonglong2*)pv)[0];
            ulonglong2 vB = ((const ulonglong2*)pv)[1];
            ulonglong2 vC = ((const ulonglong2*)pv)[2];
            ulonglong2 vD = ((const ulonglong2*)pv)[3];

            if (c < 7) {
                ull wp = pack2(w0e, w0e);
                acc0[0] = fma2(wp, vA.x, acc0[0]);
                acc0[1] = fma2(wp, vA.y, acc0[1]);
                acc0[2] = fma2(wp, vB.x, acc0[2]);
                acc0[3] = fma2(wp, vB.y, acc0[3]);
                acc0[4] = fma2(wp, vC.x, acc0[4]);
                acc0[5] = fma2(wp, vC.y, acc0[5]);
                acc0[6] = fma2(wp, vD.x, acc0[6]);
                acc0[7] = fma2(wp, vD.y, acc0[7]);
            }
            if (c >= 1) {
                ull wp = pack2(w1e, w1e);
                acc1[0] = fma2(wp, vA.x, acc1[0]);
                acc1[1] = fma2(wp, vA.y, acc1[1]);
                acc1[2] = fma2(wp, vB.x, acc1[2]);
                acc1[3] = fma2(wp, vB.y, acc1[3]);
                acc1[4] = fma2(wp, vC.x, acc1[4]);
                acc1[5] = fma2(wp, vC.y, acc1[5]);
                acc1[6] = fma2(wp, vD.x, acc1[6]);
                acc1[7] = fma2(wp, vD.y, acc1[7]);
            }
        }
    }

    const float inv0 = __fdividef(1.f, sum0);
    const float inv1 = __fdividef(1.f, sum1);

    float* op = outp + ((size_t)(b * Cc + cbase) * Hh + h) * Ww + w;
#pragma unroll
    for (int t = 0; t < 8; t++) {
        float2 a0 = unpack2(acc0[t]);
        float2 a1 = unpack2(acc1[t]);
        float2 olo = make_float2(a0.x * inv0, a1.x * inv1);
        float2 ohi = make_float2(a0.y * inv0, a1.y * inv1);
        *(float2*)(op + (2 * t) * HW)     = olo;
        *(float2*)(op + (2 * t + 1) * HW) = ohi;
    }
}

// ---------------------------------------------------------------------------
extern "C" void kernel_launch(void* const* d_in, const int* in_sizes, int n_in,
                              void* d_out, int out_size) {
    const float* x  = (const float*)d_in[0];
    const float* wq = (const float*)d_in[1];
    const float* bq = (const float*)d_in[2];
    const float* wk = (const float*)d_in[3];
    const float* bk = (const float*)d_in[4];
    const float* wv = (const float*)d_in[5];
    const float* bv = (const float*)d_in[6];
    const float* ph = (const float*)d_in[7];
    const float* pw = (const float*)d_in[8];
    float* out = (float*)d_out;

    cudaFuncSetAttribute((const void*)qkv_hmma,
                         cudaFuncAttributeMaxDynamicSharedMemorySize, GEMM_SMEM);
    const size_t attn_smem = SM_WORDS * sizeof(float);  // 113696
    cudaFuncSetAttribute((const void*)attn_kernel,
                         cudaFuncAttributeMaxDynamicSharedMemorySize, (int)attn_smem);

    qkv_hmma<<<256, 256, GEMM_SMEM>>>(x, wq, bq, wk, bk, wv, bv);
    attn_kernel<<<dim3(8, NHh, Bsz), dim3(16, 16), attn_smem>>>(bk, bv, ph, pw, out);
}

// round 14
// speedup vs baseline: 1.1508x; 1.0006x over previous
#include <cuda_runtime.h>
#include <cuda_bf16.h>
#include <cstdint>

#define Bsz 4
#define Cc  128
#define Hh  64
#define Ww  64
#define Kk  7
#define NHh 8
#define DHh 16
#define PADk 3
#define HW  (Hh*Ww)        // 4096
#define CHW (Cc*HW)        // 524288

typedef unsigned long long ull;

// scratch for projections, CHANNEL-LAST layout [b][hw][c]
__device__ float g_q[Bsz*CHW];
__device__ float g_k[Bsz*CHW];
__device__ float g_v[Bsz*CHW];

#define LDK 136                          // padded bf16 row length (272 B)

// ---------------- packed f32x2 helpers ----------------
__device__ __forceinline__ ull fma2(ull a, ull b, ull c) {
    ull d; asm("fma.rn.f32x2 %0, %1, %2, %3;" : "=l"(d) : "l"(a), "l"(b), "l"(c)); return d;
}
__device__ __forceinline__ ull add2(ull a, ull b) {
    ull d; asm("add.rn.f32x2 %0, %1, %2;" : "=l"(d) : "l"(a), "l"(b)); return d;
}
__device__ __forceinline__ ull pack2(float lo, float hi) {
    ull d; asm("mov.b64 %0, {%1, %2};" : "=l"(d) : "f"(lo), "f"(hi)); return d;
}
__device__ __forceinline__ float2 unpack2(ull v) {
    float2 r; asm("mov.b64 {%0, %1}, %2;" : "=f"(r.x), "=f"(r.y) : "l"(v)); return r;
}

// ---------------- HMMA helpers (sm_80+) ----------------
__device__ __forceinline__ uint32_t smem_u32(const void* p) {
    uint32_t a;
    asm("{ .reg .u64 t; cvta.to.shared.u64 t, %1; cvt.u32.u64 %0, t; }" : "=r"(a) : "l"(p));
    return a;
}
__device__ __forceinline__ void ldsm_x4(uint32_t& r0, uint32_t& r1, uint32_t& r2,
                                        uint32_t& r3, uint32_t addr) {
    asm volatile("ldmatrix.sync.aligned.m8n8.x4.shared.b16 {%0,%1,%2,%3}, [%4];"
                 : "=r"(r0), "=r"(r1), "=r"(r2), "=r"(r3) : "r"(addr));
}
__device__ __forceinline__ void mma_bf16(float* c, const uint32_t* a, const uint32_t* b) {
    asm volatile(
        "mma.sync.aligned.m16n8k16.row.col.f32.bf16.bf16.f32 "
        "{%0,%1,%2,%3}, {%4,%5,%6,%7}, {%8,%9}, {%0,%1,%2,%3};"
        : "+f"(c[0]), "+f"(c[1]), "+f"(c[2]), "+f"(c[3])
        : "r"(a[0]), "r"(a[1]), "r"(a[2]), "r"(a[3]), "r"(b[0]), "r"(b[1]));
}

// ---------------------------------------------------------------------------
// Kernel 1 (R13, proven): fused QKV GEMM via HMMA (bf16 hi/lo, 3 terms),
// W converted in-block. Grid = 256 (64 px, 2 blocks/SM). 8 warps (4m x 2n).
// ---------------------------------------------------------------------------
#define XHI_OFF 0
#define XLO_OFF (64 * LDK * 2)          // 17408
#define WHI_OFF (2 * 64 * LDK * 2)      // 34816
#define WLO_OFF (WHI_OFF + 128 * LDK * 2)
#define GEMM_SMEM (WHI_OFF + 2 * 128 * LDK * 2)   // 104448 B

__global__ __launch_bounds__(256, 2) void qkv_hmma(
    const float* __restrict__ x,
    const float* __restrict__ wq, const float* __restrict__ bq,
    const float* __restrict__ wk, const float* __restrict__ bk,
    const float* __restrict__ wv, const float* __restrict__ bv)
{
    extern __shared__ char smc[];
    unsigned short* Xhi = (unsigned short*)(smc + XHI_OFF);
    unsigned short* Xlo = (unsigned short*)(smc + XLO_OFF);
    unsigned short* Whi = (unsigned short*)(smc + WHI_OFF);
    unsigned short* Wlo = (unsigned short*)(smc + WLO_OFF);
    const uint32_t sb = smem_u32(smc);

    const int tid = threadIdx.x;
    const int warp = tid >> 5, lane = tid & 31;
    const int wy = warp >> 1, wx = warp & 1;   // m = wy*32, n = wx*32
    const int n0 = blockIdx.x * 64;
    const int b = n0 >> 12, hw0 = n0 & 4095;
    const float* xb = x + (size_t)b * CHW + hw0;

    // ---- X tile (64 px): fp32 -> bf16 hi/lo, [n][k] ----
    for (int e = tid; e < 8192; e += 256) {
        int c = e >> 6, n = e & 63;
        float v = xb[c * HW + n];
        __nv_bfloat16 h = __float2bfloat16(v);
        __nv_bfloat16 l = __float2bfloat16(v - __bfloat162float(h));
        Xhi[n * LDK + c] = __bfloat16_as_ushort(h);
        Xlo[n * LDK + c] = __bfloat16_as_ushort(l);
    }

#pragma unroll 1
    for (int p = 0; p < 3; p++) {
        const float* Wp = (p == 0) ? wq : (p == 1) ? wk : wv;
        const float* bp = (p == 0) ? bq : (p == 1) ? bk : bv;
        float* og = ((p == 0) ? g_q : (p == 1) ? g_k : g_v) + (size_t)n0 * 128;

        __syncthreads();   // X ready (p=0); prior mma reads of W done (p>0)
        // ---- convert W(p) fp32 -> bf16 hi/lo into smem (coalesced) ----
        for (int e = tid * 4; e < 16384; e += 1024) {
            int m = e >> 7, c = e & 127;
            float4 v4 = *(const float4*)&Wp[e];
            ushort4 h4, l4;
            __nv_bfloat16 h;
            h = __float2bfloat16(v4.x); h4.x = __bfloat16_as_ushort(h);
            l4.x = __bfloat16_as_ushort(__float2bfloat16(v4.x - __bfloat162float(h)));
            h = __float2bfloat16(v4.y); h4.y = __bfloat16_as_ushort(h);
            l4.y = __bfloat16_as_ushort(__float2bfloat16(v4.y - __bfloat162float(h)));
            h = __float2bfloat16(v4.z); h4.z = __bfloat16_as_ushort(h);
            l4.z = __bfloat16_as_ushort(__float2bfloat16(v4.z - __bfloat162float(h)));
            h = __float2bfloat16(v4.w); h4.w = __bfloat16_as_ushort(h);
            l4.w = __bfloat16_as_ushort(__float2bfloat16(v4.w - __bfloat162float(h)));
            *(ushort4*)&Whi[m * LDK + c] = h4;
            *(ushort4*)&Wlo[m * LDK + c] = l4;
        }
        __syncthreads();

        float acc[2][4][4];
#pragma unroll
        for (int i = 0; i < 2; i++)
#pragma unroll
            for (int j = 0; j < 4; j++)
#pragma unroll
                for (int t = 0; t < 4; t++) acc[i][j][t] = 0.f;

#pragma unroll
        for (int k = 0; k < 8; k++) {
            const int kb = k * 16;
            uint32_t ahi[2][4], alo[2][4];
#pragma unroll
            for (int mf = 0; mf < 2; mf++) {
                int row = wy * 32 + mf * 16 + (lane & 15);
                int col = kb + ((lane >> 4) << 3);
                uint32_t off = (uint32_t)(row * LDK + col) * 2;
                ldsm_x4(ahi[mf][0], ahi[mf][1], ahi[mf][2], ahi[mf][3],
                        sb + WHI_OFF + off);
                ldsm_x4(alo[mf][0], alo[mf][1], alo[mf][2], alo[mf][3],
                        sb + WLO_OFF + off);
            }
            uint32_t bhi[4][2], blo[4][2];
#pragma unroll
            for (int nf4 = 0; nf4 < 2; nf4++) {
                int g = lane >> 3;
                int row = wx * 32 + nf4 * 16 + (lane & 7) + ((g & 2) << 2);
                int col = kb + ((g & 1) << 3);
                uint32_t off = (uint32_t)(row * LDK + col) * 2;
                uint32_t r0, r1, r2, r3;
                ldsm_x4(r0, r1, r2, r3, sb + XHI_OFF + off);
                bhi[nf4 * 2][0] = r0; bhi[nf4 * 2][1] = r1;
                bhi[nf4 * 2 + 1][0] = r2; bhi[nf4 * 2 + 1][1] = r3;
                ldsm_x4(r0, r1, r2, r3, sb + XLO_OFF + off);
                blo[nf4 * 2][0] = r0; blo[nf4 * 2][1] = r1;
                blo[nf4 * 2 + 1][0] = r2; blo[nf4 * 2 + 1][1] = r3;
            }
#pragma unroll
            for (int mf = 0; mf < 2; mf++)
#pragma unroll
                for (int nf = 0; nf < 4; nf++) {
                    mma_bf16(acc[mf][nf], ahi[mf], bhi[nf]);
                    mma_bf16(acc[mf][nf], ahi[mf], blo[nf]);
                    mma_bf16(acc[mf][nf], alo[mf], bhi[nf]);
                }
        }

        // ---- epilogue: channel-last store ----
#pragma unroll
        for (int mf = 0; mf < 2; mf++) {
            int r0 = wy * 32 + mf * 16 + (lane >> 2);
            int r1 = r0 + 8;
            float bi0 = bp[r0], bi1 = bp[r1];
#pragma unroll
            for (int nf = 0; nf < 4; nf++) {
                int c0 = wx * 32 + nf * 8 + (lane & 3) * 2;
                float* o0 = og + (size_t)c0 * 128;
                float* o1 = o0 + 128;
                o0[r0] = acc[mf][nf][0] + bi0;
                o1[r0] = acc[mf][nf][1] + bi0;
                o0[r1] = acc[mf][nf][2] + bi1;
                o1[r1] = acc[mf][nf][3] + bi1;
            }
        }
    }
}

// ---------------------------------------------------------------------------
// Kernel 2: local attention — R13 config, inner loop restructured into
// sequential K-half / V-half phases reusing ONE pair of 128-bit temporaries,
// cutting peak transient registers 32 -> 8 so ptxas can pipeline c-iterations
// under the 128-reg cap. Math is operation-identical to R13.
// ---------------------------------------------------------------------------
#define RSTRIDE 1292             // 19 * 68
#define HROWS 22
#define SM_WORDS (HROWS * RSTRIDE) // 113696 B

__global__ __launch_bounds__(256, 2) void attn_kernel(
    const float* __restrict__ bk, const float* __restrict__ bv,
    const float* __restrict__ pos_h, const float* __restrict__ pos_w,
    float* __restrict__ outp)
{
    extern __shared__ float sm[];
    __shared__ float ehw[52];

    const int tr = blockIdx.x >> 1, tc = blockIdx.x & 1;
    const int h0 = tr * 16, w0 = tc * 32;
    const int nh = blockIdx.y, b = blockIdx.z;
    const int tx = threadIdx.x, ty = threadIdx.y;
    const int tid = ty * 16 + tx;
    const int cbase = nh * DHh;

    const float* kb = g_k + (size_t)b * CHW + cbase;
    const float* vb = g_v + (size_t)b * CHW + cbase;

    if (tid < 49)
        ehw[tid] = __expf(pos_h[nh * 7 + tid / 7] + pos_w[nh * 7 + tid % 7]);

    // ---- q loads issued before the barrier (overlap with halo fill) ----
    const int h = h0 + ty, w = w0 + 2 * tx;
    const float* qp = g_q + (size_t)b * CHW + (size_t)(h * Ww + w) * Cc + cbase;
    float4 qf0[4], qf1[4];
#pragma unroll
    for (int t = 0; t < 4; t++) {
        qf0[t] = *(const float4*)(qp + t * 4);
        qf1[t] = *(const float4*)(qp + Cc + t * 4);
    }

    // ---- fill halo: 22 x 38 sites x 4 quads (float4), K+V per iter ----
    for (int idx = tid; idx < HROWS * 38 * 4; idx += 256) {
        int quad = idx & 3;
        int site = idx >> 2;
        int r = site / 38, c = site - r * 38;
        int gh = h0 - PADk + r, gw = w0 - PADk + c;
        float4 kq, vq;
        if ((unsigned)gh < (unsigned)Hh && (unsigned)gw < (unsigned)Ww) {
            size_t g = (size_t)(gh * Ww + gw) * Cc + quad * 4;
            kq = *(const float4*)(kb + g);
            vq = *(const float4*)(vb + g);
        } else {
            kq = *(const float4*)(bk + cbase + quad * 4);
            vq = *(const float4*)(bv + cbase + quad * 4);
        }
        int off = r * RSTRIDE + (c >> 1) * 68 + (c & 1) * 16 + quad * 4;
        *(float4*)(sm + off)      = kq;
        *(float4*)(sm + off + 32) = vq;
    }
    __syncthreads();

    __nanosleep((tid >> 5) * 40);

    ull q0p[8], q1p[8];
#pragma unroll
    for (int t = 0; t < 4; t++) {
        q0p[2 * t]     = pack2(qf0[t].x, qf0[t].y);
        q0p[2 * t + 1] = pack2(qf0[t].z, qf0[t].w);
        q1p[2 * t]     = pack2(qf1[t].x, qf1[t].y);
        q1p[2 * t + 1] = pack2(qf1[t].z, qf1[t].w);
    }

    ull acc0[8], acc1[8];
#pragma unroll
    for (int t = 0; t < 8; t++) { acc0[t] = 0ull; acc1[t] = 0ull; }
    float sum0 = 0.f, sum1 = 0.f;

#pragma unroll 1
    for (int i = 0; i < 7; i++) {
        const float* rowp = sm + (ty + i) * RSTRIDE;
        const float* eh_row = ehw + i * 7;
#pragma unroll
        for (int c = 0; c < 8; c++) {
            const float* p = rowp + (tx + (c >> 1)) * 68 + (c & 1) * 16;

            // --- phase 1: K low half (d0..7) ---
            ulonglong2 t0 = ((const ulonglong2*)p)[0];
            ulonglong2 t1 = ((const ulonglong2*)p)[1];
            ull s0A = fma2(q0p[0], t0.x, 0ull);
            ull s0B = fma2(q0p[1], t0.y, 0ull);
            ull s1A = fma2(q1p[0], t0.x, 0ull);
            ull s1B = fma2(q1p[1], t0.y, 0ull);
            s0A = fma2(q0p[2], t1.x, s0A);
            s0B = fma2(q0p[3], t1.y, s0B);
            s1A = fma2(q1p[2], t1.x, s1A);
            s1B = fma2(q1p[3], t1.y, s1B);

            // --- phase 2: K high half (d8..15), reuse temporaries ---
            t0 = ((const ulonglong2*)p)[2];
            t1 = ((const ulonglong2*)p)[3];
            s0A = fma2(q0p[4], t0.x, s0A);
            s0B = fma2(q0p[5], t0.y, s0B);
            s1A = fma2(q1p[4], t0.x, s1A);
            s1B = fma2(q1p[5], t0.y, s1B);
            s0A = fma2(q0p[6], t1.x, s0A);
            s0B = fma2(q0p[7], t1.y, s0B);
            s1A = fma2(q1p[6], t1.x, s1A);
            s1B = fma2(q1p[7], t1.y, s1B);

            float w0e = 0.f, w1e = 0.f;
            if (c < 7) {   // pixel0 neighbor j = c
                float2 f = unpack2(add2(s0A, s0B));
                w0e = __expf(f.x + f.y) * eh_row[c];
                sum0 += w0e;
            }
            if (c >= 1) {  // pixel1 neighbor j = c-1
                float2 f = unpack2(add2(s1A, s1B));
                w1e = __expf(f.x + f.y) * eh_row[c - 1];
                sum1 += w1e;
            }
            ull wp0 = pack2(w0e, w0e);
            ull wp1 = pack2(w1e, w1e);

            // --- phase 3: V low half ---
            const float* pv = p + 32;
            t0 = ((const ulonglong2*)pv)[0];
            t1 = ((const ulonglong2*)pv)[1];
            if (c < 7) {
                acc0[0] = fma2(wp0, t0.x, acc0[0]);
                acc0[1] = fma2(wp0, t0.y, acc0[1]);
                acc0[2] = fma2(wp0, t1.x, acc0[2]);
                acc0[3] = fma2(wp0, t1.y, acc0[3]);
            }
            if (c >= 1) {
                acc1[0] = fma2(wp1, t0.x, acc1[0]);
                acc1[1] = fma2(wp1, t0.y, acc1[1]);
                acc1[2] = fma2(wp1, t1.x, acc1[2]);
                acc1[3] = fma2(wp1, t1.y, acc1[3]);
            }

            // --- phase 4: V high half, reuse temporaries ---
            t0 = ((const ulonglong2*)pv)[2];
            t1 = ((const ulonglong2*)pv)[3];
            if (c < 7) {
                acc0[4] = fma2(wp0, t0.x, acc0[4]);
                acc0[5] = fma2(wp0, t0.y, acc0[5]);
                acc0[6] = fma2(wp0, t1.x, acc0[6]);
                acc0[7] = fma2(wp0, t1.y, acc0[7]);
            }
            if (c >= 1) {
                acc1[4] = fma2(wp1, t0.x, acc1[4]);
                acc1[5] = fma2(wp1, t0.y, acc1[5]);
                acc1[6] = fma2(wp1, t1.x, acc1[6]);
                acc1[7] = fma2(wp1, t1.y, acc1[7]);
            }
        }
    }

    const float inv0 = __fdividef(1.f, sum0);
    const float inv1 = __fdividef(1.f, sum1);

    float* op = outp + ((size_t)(b * Cc + cbase) * Hh + h) * Ww + w;
#pragma unroll
    for (int t = 0; t < 8; t++) {
        float2 a0 = unpack2(acc0[t]);
        float2 a1 = unpack2(acc1[t]);
        float2 olo = make_float2(a0.x * inv0, a1.x * inv1);
        float2 ohi = make_float2(a0.y * inv0, a1.y * inv1);
        *(float2*)(op + (2 * t) * HW)     = olo;
        *(float2*)(op + (2 * t + 1) * HW) = ohi;
    }
}

// ---------------------------------------------------------------------------
extern "C" void kernel_launch(void* const* d_in, const int* in_sizes, int n_in,
                              void* d_out, int out_size) {
    const float* x  = (const float*)d_in[0];
    const float* wq = (const float*)d_in[1];
    const float* bq = (const float*)d_in[2];
    const float* wk = (const float*)d_in[3];
    const float* bk = (const float*)d_in[4];
    const float* wv = (const float*)d_in[5];
    const float* bv = (const float*)d_in[6];
    const float* ph = (const float*)d_in[7];
    const float* pw = (const float*)d_in[8];
    float* out = (float*)d_out;

    cudaFuncSetAttribute((const void*)qkv_hmma,
                         cudaFuncAttributeMaxDynamicSharedMemorySize, GEMM_SMEM);
    const size_t attn_smem = SM_WORDS * sizeof(float);  // 113696
    cudaFuncSetAttribute((const void*)attn_kernel,
                         cudaFuncAttributeMaxDynamicSharedMemorySize, (int)attn_smem);

    qkv_hmma<<<256, 256, GEMM_SMEM>>>(x, wq, bq, wk, bk, wv, bv);
    attn_kernel<<<dim3(8, NHh, Bsz), dim3(16, 16), attn_smem>>>(bk, bv, ph, pw, out);
}